// round 9
// baseline (speedup 1.0000x reference)
#include <cuda_runtime.h>

#define BB 2
#define HH 160
#define WW 160
#define NPTS 2048
#define HW (HH*WW)
#define TOTAL (BB*HW)        // 51200
#define NV4 (TOTAL/4)        // 12800 float4s
#define NTHR 256
#define NBLK 50              // 50*256 = 12800 float4s exactly (no tail)
#define PIX_PER_BLK (NTHR*4) // 1024 pixels per block slice
#define NPT (BB*NPTS)        // 4096 points
#define PPT (NPT/NTHR)       // 16 points/thread
#define LMASKW (PIX_PER_BLK/32)  // 32 words local mask
#define DOWN 16.0f
#define HALF 7.5f
#define INV  (1.0f/16.0f)

__device__ float    g_partials[NBLK];
__device__ unsigned g_count;   // zero-init; acq_rel inc wraps -> self-resets each replay

__device__ __forceinline__ float warp_sum(float v) {
    #pragma unroll
    for (int o = 16; o > 0; o >>= 1) v += __shfl_down_sync(0xffffffffu, v, o);
    return v;
}

// softplus(a) = max(a,0) + log1p(exp(-|a|)); fast fp32 MUFU version
__device__ __forceinline__ float softplus(float a) {
    return fmaxf(a, 0.0f) + __logf(1.0f + __expf(-fabsf(a)));
}

// acq_rel atomicInc: orders this block's prior store (release) and the last
// arrival's subsequent loads (acquire) without a full MEMBAR.GPU / L1 flush.
__device__ __forceinline__ unsigned atomicInc_acqrel(unsigned* p, unsigned b) {
    unsigned old;
    asm volatile("atom.acq_rel.gpu.global.inc.u32 %0, [%1], %2;"
                 : "=r"(old) : "l"(p), "r"(b) : "memory");
    return old;
}

// nearest pixel-center index along one axis: round((p-7.5)/16), clamped.
// 1/16 is an exact power of two; only a measure-zero tie window can differ
// from the reference's fp32 min-distance pick (and a flip shifts the loss
// by ~2e-5 relative, far under tolerance).
__device__ __forceinline__ int nearest_idx(float p, int lim) {
    int i = __float2int_rn(fmaf(p, INV, -(HALF * INV)));
    return min(max(i, 0), lim);
}

__global__ __launch_bounds__(NTHR, 1)
void p2r_fused(const float* __restrict__ dens, const float* __restrict__ pts,
               float* __restrict__ out) {
    __shared__ float    s_red[NTHR / 32];
    __shared__ unsigned s_mask[LMASKW];   // bit per pixel of THIS block's slice

    const int tid  = threadIdx.x;
    const int lane = tid & 31;
    const int w    = tid >> 5;
    const int bid  = blockIdx.x;

    // ---- issue this thread's dense load (1 float4 = 4 pixels) ----
    const float4 a = ((const float4*)dens)[bid * NTHR + tid];   // exact cover

    // ---- issue point loads: 16 points = 8 float4 (L2-hot, front-batched) ----
    const float4* p4 = (const float4*)pts;
    float4 pp[PPT / 2];
    #pragma unroll
    for (int q = 0; q < PPT / 2; q++) pp[q] = p4[tid * (PPT / 2) + q];

    // zero local mask while loads are in flight; BARRIER before any atomicOr
    if (tid < LMASKW) s_mask[tid] = 0u;
    __syncthreads();

    // ---- rasterize: mark points whose nearest pixel falls in MY slice ----
    const int b    = tid >> 7;            // 16-pt runs never straddle batch edge
    const int base = bid * PIX_PER_BLK;   // my slice: [base, base+1024)
    #pragma unroll
    for (int q = 0; q < PPT / 2; q++) {
        #pragma unroll
        for (int h = 0; h < 2; h++) {
            const float p0 = h ? pp[q].z : pp[q].x;   // y
            const float p1 = h ? pp[q].w : pp[q].y;   // x
            const int iy = nearest_idx(p0, HH - 1);
            const int ix = nearest_idx(p1, WW - 1);
            const float dy = fmaf((float)iy, DOWN, HALF) - p0;
            const float dx = fmaf((float)ix, DOWN, HALF) - p1;
            // sqrtf(d2) < 8  <=>  d2 < 64 (sqrt monotone, correctly rounded)
            const int off = b * HW + iy * WW + ix - base;
            if ((dy * dy + dx * dx) < 64.0f && (unsigned)off < PIX_PER_BLK)
                atomicOr(&s_mask[off >> 5], 1u << (off & 31));  // same-value races OK
        }
    }
    __syncthreads();

    // ---- fold: softplus(A) + [marked]*(softplus(A) - 2A) over my 4 pixels ----
    const unsigned m = s_mask[tid >> 3] >> ((tid & 7) * 4);   // my 4 bits
    float v = 0.0f, sp;
    sp = softplus(a.x); v += sp + ((m & 1u) ? sp - 2.0f * a.x : 0.0f);
    sp = softplus(a.y); v += sp + ((m & 2u) ? sp - 2.0f * a.y : 0.0f);
    sp = softplus(a.z); v += sp + ((m & 4u) ? sp - 2.0f * a.z : 0.0f);
    sp = softplus(a.w); v += sp + ((m & 8u) ? sp - 2.0f * a.w : 0.0f);

    // ---- block reduce -> one L2 store + one acq_rel atomic per block ----
    v = warp_sum(v);
    if (lane == 0) s_red[w] = v;
    __syncthreads();
    if (w != 0) return;
    v = (lane < NTHR / 32) ? s_red[lane] : 0.0f;
    #pragma unroll
    for (int o = 4; o > 0; o >>= 1) v += __shfl_down_sync(0xffu, v, o);

    unsigned old = 0;
    if (lane == 0) {
        __stcg(&g_partials[bid], v);                  // straight to L2
        old = atomicInc_acqrel(&g_count, NBLK - 1);   // wraps to 0 on last
    }
    old = __shfl_sync(0xffffffffu, old, 0);
    if (old == NBLK - 1) {
        // last arrival: gather 50 partials (2 per lane), reduce, write
        float p = __ldcg(&g_partials[lane]);
        if (lane + 32 < NBLK) p += __ldcg(&g_partials[lane + 32]);
        p = warp_sum(p);
        if (lane == 0) out[0] = p * (1.0f / (float)TOTAL);
    }
}

extern "C" void kernel_launch(void* const* d_in, const int* in_sizes, int n_in,
                              void* d_out, int out_size) {
    const float* dens = (const float*)d_in[0];
    const float* pts  = (const float*)d_in[1];
    p2r_fused<<<NBLK, NTHR>>>(dens, pts, (float*)d_out);
}

// round 10
// speedup vs baseline: 1.7931x; 1.7931x over previous
#include <cuda_runtime.h>

#define BB 2
#define HH 160
#define WW 160
#define NPTS 2048
#define HW (HH*WW)
#define TOTAL (BB*HW)        // 51200
#define NV4 (TOTAL/4)        // 12800 float4s
#define NTHR 1024
#define NBLK 13              // 13*1024 = 13312 float4 slots >= 12800
#define PIX_PER_BLK (NTHR*4) // 4096 pixels per block slice
#define NPT (BB*NPTS)        // 4096 points
#define PPT (NPT/NTHR)       // 4 points/thread
#define LMASKW (PIX_PER_BLK/32)  // 128 words
#define DOWN 16.0f
#define HALF 7.5f
#define INV  (1.0f/16.0f)
#define FSCALE 1048576.0f    // 2^20 fixed-point scale
#define BIAS   (1LL << 40)   // keeps each block's addend positive
#define CNT_SHIFT 52
#define VAL_MASK ((1ULL << 52) - 1)

// Single packed accumulator: {count:12 | biased sum:52}. Zero-init; the last
// block resets it with atomicExch, so every graph replay starts clean.
__device__ unsigned long long g_pack;

__device__ __forceinline__ float warp_sum(float v) {
    #pragma unroll
    for (int o = 16; o > 0; o >>= 1) v += __shfl_down_sync(0xffffffffu, v, o);
    return v;
}

// softplus(a) = max(a,0) + log1p(exp(-|a|)); fast fp32 MUFU version
__device__ __forceinline__ float softplus(float a) {
    return fmaxf(a, 0.0f) + __logf(1.0f + __expf(-fabsf(a)));
}

// nearest pixel-center along one axis as float (rint of (p-7.5)/16, clamped).
// 1/16 exact power of two; only a measure-zero tie window can differ from the
// reference's fp32 min-distance pick (loss shift ~2e-5 rel even if flipped).
__device__ __forceinline__ float nearest_f(float p, float lim) {
    float fi = rintf(fmaf(p, INV, -(HALF * INV)));
    return fminf(fmaxf(fi, 0.0f), lim);
}

__global__ __launch_bounds__(NTHR, 1)
void p2r_fused(const float* __restrict__ dens, const float* __restrict__ pts,
               float* __restrict__ out) {
    __shared__ unsigned long long s_acc;     // integer -> deterministic
    __shared__ unsigned s_mask[LMASKW];      // bit per pixel of THIS slice

    const int tid  = threadIdx.x;
    const int lane = tid & 31;
    const int bid  = blockIdx.x;

    // ---- issue dense load (1 float4 = 4 pixels) immediately ----
    const int fi = bid * NTHR + tid;
    const bool valid = fi < NV4;
    float4 a = valid ? ((const float4*)dens)[fi] : make_float4(0.f, 0.f, 0.f, 0.f);

    // ---- issue point loads (4 points = 2 float4, L2-hot) ----
    const float4* p4 = (const float4*)pts;
    float4 pp0 = p4[2 * tid];
    float4 pp1 = p4[2 * tid + 1];

    // zero mask + accumulator while loads are in flight; BARRIER before atomicOr
    if (tid < LMASKW) s_mask[tid] = 0u;
    if (tid == 0) s_acc = 0ULL;
    __syncthreads();

    // ---- rasterize: mark points whose nearest pixel falls in MY slice ----
    const int b    = tid >> 9;             // points 4t..4t+3 share batch
    const int base = bid * PIX_PER_BLK;    // my slice: [base, base+4096)
    #pragma unroll
    for (int q = 0; q < 2; q++) {
        const float4 pq = q ? pp1 : pp0;
        #pragma unroll
        for (int h = 0; h < 2; h++) {
            const float p0 = h ? pq.z : pq.x;   // y
            const float p1 = h ? pq.w : pq.y;   // x
            const float fy = nearest_f(p0, (float)(HH - 1));
            const float fx = nearest_f(p1, (float)(WW - 1));
            const float dy = fmaf(fy, DOWN, HALF) - p0;
            const float dx = fmaf(fx, DOWN, HALF) - p1;
            // sqrtf(d2) < 8  <=>  d2 < 64 (sqrt monotone, correctly rounded)
            const int off = b * HW + (int)fy * WW + (int)fx - base;
            if ((dy * dy + dx * dx) < 64.0f && (unsigned)off < PIX_PER_BLK)
                atomicOr(&s_mask[off >> 5], 1u << (off & 31));  // same-value races OK
        }
    }
    __syncthreads();

    // ---- fold: softplus(A) + [marked]*(softplus(A) - 2A) over my 4 pixels ----
    float v = 0.0f;
    if (valid) {
        const unsigned m = s_mask[tid >> 3] >> ((tid & 7) * 4);  // my 4 bits
        float sp;
        sp = softplus(a.x); v += sp + ((m & 1u) ? sp - 2.0f * a.x : 0.0f);
        sp = softplus(a.y); v += sp + ((m & 2u) ? sp - 2.0f * a.y : 0.0f);
        sp = softplus(a.z); v += sp + ((m & 4u) ? sp - 2.0f * a.z : 0.0f);
        sp = softplus(a.w); v += sp + ((m & 8u) ? sp - 2.0f * a.w : 0.0f);
    }

    // ---- warp reduce -> per-warp fixed-point add into smem (deterministic) ----
    v = warp_sum(v);
    if (lane == 0)
        atomicAdd(&s_acc, (unsigned long long)(long long)__float2ll_rn(v * FSCALE));
    __syncthreads();

    // ---- ONE global atomic: {count|sum} packed; winner holds the full sum ----
    if (tid == 0) {
        const long long iv = (long long)s_acc;
        const unsigned long long ticket =
            (1ULL << CNT_SHIFT) + (unsigned long long)(iv + BIAS);
        const unsigned long long old = atomicAdd(&g_pack, ticket);
        if ((unsigned)(old >> CNT_SHIFT) == NBLK - 1) {   // I'm the last arrival
            const unsigned long long full = old + ticket; // complete packed sum
            const long long s =
                (long long)(full & VAL_MASK) - (long long)NBLK * BIAS;
            out[0] = (float)s * (1.0f / FSCALE) * (1.0f / (float)TOTAL);
            atomicExch(&g_pack, 0ULL);                    // reset for next replay
        }
    }
}

extern "C" void kernel_launch(void* const* d_in, const int* in_sizes, int n_in,
                              void* d_out, int out_size) {
    const float* dens = (const float*)d_in[0];
    const float* pts  = (const float*)d_in[1];
    p2r_fused<<<NBLK, NTHR>>>(dens, pts, (float*)d_out);
}

// round 11
// speedup vs baseline: 1.9339x; 1.0785x over previous
#include <cuda_runtime.h>

#define BB 2
#define HH 160
#define WW 160
#define NPTS 2048
#define HW (HH*WW)
#define TOTAL (BB*HW)        // 51200
#define NV4 (TOTAL/4)        // 12800 float4s
#define NTHR 1024
#define NBLK 13              // 13*1024 = 13312 float4 slots >= 12800
#define PIX_PER_BLK (NTHR*4) // 4096 pixels per block slice
#define LMASKW (PIX_PER_BLK/32)  // 128 words
#define DOWN 16.0f
#define HALF 7.5f
#define INV  (1.0f/16.0f)
#define FSCALE 1048576.0f    // 2^20 fixed-point scale
#define BIAS   (1LL << 40)   // keeps each block's addend positive
#define CNT_SHIFT 52
#define VAL_MASK ((1ULL << 52) - 1)

// Single packed accumulator: {count:12 | biased sum:52}. Zero-init; the last
// block resets it with atomicExch, so every graph replay starts clean.
__device__ unsigned long long g_pack;

__device__ __forceinline__ float warp_sum(float v) {
    #pragma unroll
    for (int o = 16; o > 0; o >>= 1) v += __shfl_down_sync(0xffffffffu, v, o);
    return v;
}

// softplus(a) = max(a,0) + log1p(exp(-|a|)); fast fp32 MUFU version
__device__ __forceinline__ float softplus(float a) {
    return fmaxf(a, 0.0f) + __logf(1.0f + __expf(-fabsf(a)));
}

// nearest pixel-center along one axis as float (rint of (p-7.5)/16, clamped).
// 1/16 exact power of two; only a measure-zero tie window can differ from the
// reference's fp32 min-distance pick (loss shift ~2e-5 rel even if flipped).
__device__ __forceinline__ float nearest_f(float p, float lim) {
    float fi = rintf(fmaf(p, INV, -(HALF * INV)));
    return fminf(fmaxf(fi, 0.0f), lim);
}

__global__ __launch_bounds__(NTHR, 1)
void p2r_fused(const float* __restrict__ dens, const float* __restrict__ pts,
               float* __restrict__ out) {
    __shared__ float    s_red[NTHR / 32];    // 32 per-warp partials, no conflicts
    __shared__ unsigned s_mask[LMASKW];      // bit per pixel of THIS slice

    const int tid  = threadIdx.x;
    const int lane = tid & 31;
    const int w    = tid >> 5;
    const int bid  = blockIdx.x;

    // ---- issue dense load (1 float4 = 4 pixels) immediately ----
    const int fi = bid * NTHR + tid;
    const bool valid = fi < NV4;
    float4 a = valid ? ((const float4*)dens)[fi] : make_float4(0.f, 0.f, 0.f, 0.f);

    // ---- issue point loads (4 points = 2 float4, L2-hot) ----
    const float4* p4 = (const float4*)pts;
    float4 pp0 = p4[2 * tid];
    float4 pp1 = p4[2 * tid + 1];

    // zero mask while loads are in flight; BARRIER before any atomicOr
    if (tid < LMASKW) s_mask[tid] = 0u;
    __syncthreads();

    // ---- rasterize: mark points whose nearest pixel falls in MY slice ----
    const int b    = tid >> 9;             // points 4t..4t+3 share batch
    const int base = bid * PIX_PER_BLK;    // my slice: [base, base+4096)
    #pragma unroll
    for (int q = 0; q < 2; q++) {
        const float4 pq = q ? pp1 : pp0;
        #pragma unroll
        for (int h = 0; h < 2; h++) {
            const float p0 = h ? pq.z : pq.x;   // y
            const float p1 = h ? pq.w : pq.y;   // x
            const float fy = nearest_f(p0, (float)(HH - 1));
            const float fx = nearest_f(p1, (float)(WW - 1));
            const float dy = fmaf(fy, DOWN, HALF) - p0;
            const float dx = fmaf(fx, DOWN, HALF) - p1;
            // sqrtf(d2) < 8  <=>  d2 < 64 (sqrt monotone, correctly rounded)
            const int off = b * HW + (int)fy * WW + (int)fx - base;
            if ((dy * dy + dx * dx) < 64.0f && (unsigned)off < PIX_PER_BLK)
                atomicOr(&s_mask[off >> 5], 1u << (off & 31));  // same-value races OK
        }
    }
    __syncthreads();

    // ---- fold: softplus(A) + [marked]*(softplus(A) - 2A) over my 4 pixels ----
    float v = 0.0f;
    if (valid) {
        const unsigned m = s_mask[tid >> 3] >> ((tid & 7) * 4);  // my 4 bits
        float sp;
        sp = softplus(a.x); v += sp + ((m & 1u) ? sp - 2.0f * a.x : 0.0f);
        sp = softplus(a.y); v += sp + ((m & 2u) ? sp - 2.0f * a.y : 0.0f);
        sp = softplus(a.z); v += sp + ((m & 4u) ? sp - 2.0f * a.z : 0.0f);
        sp = softplus(a.w); v += sp + ((m & 8u) ? sp - 2.0f * a.w : 0.0f);
    }

    // ---- block reduce: per-warp shfl tree -> s_red -> warp0 shfl tree ----
    // (fixed reduction order -> bitwise deterministic; no smem atomic chain)
    v = warp_sum(v);
    if (lane == 0) s_red[w] = v;
    __syncthreads();
    if (w != 0) return;
    v = warp_sum(s_red[lane]);           // NTHR/32 == 32: all lanes valid

    // ---- ONE global atomic: {count|sum} packed; winner holds the full sum ----
    if (lane == 0) {
        const long long iv = (long long)__float2ll_rn(v * FSCALE);
        const unsigned long long ticket =
            (1ULL << CNT_SHIFT) + (unsigned long long)(iv + BIAS);
        const unsigned long long old = atomicAdd(&g_pack, ticket);
        if ((unsigned)(old >> CNT_SHIFT) == NBLK - 1) {   // I'm the last arrival
            const unsigned long long full = old + ticket; // complete packed sum
            const long long s =
                (long long)(full & VAL_MASK) - (long long)NBLK * BIAS;
            out[0] = (float)s * (1.0f / FSCALE) * (1.0f / (float)TOTAL);
            atomicExch(&g_pack, 0ULL);                    // reset for next replay
        }
    }
}

extern "C" void kernel_launch(void* const* d_in, const int* in_sizes, int n_in,
                              void* d_out, int out_size) {
    const float* dens = (const float*)d_in[0];
    const float* pts  = (const float*)d_in[1];
    p2r_fused<<<NBLK, NTHR>>>(dens, pts, (float*)d_out);
}